// round 2
// baseline (speedup 1.0000x reference)
#include <cuda_runtime.h>
#include <math.h>

#define BB 8
#define DD 256
#define NL 10000
#define KN 32
#define KC 10032
#define NS 100
#define LISTCAP 1024

// scratch (no allocations allowed)
__device__ float g_logits[BB * KC];
__device__ float g_boot[NS * BB * DD];

// ---------- block reductions (256 threads) ----------
__device__ __forceinline__ float blockMax(float v, float* red) {
#pragma unroll
    for (int o = 16; o; o >>= 1) v = fmaxf(v, __shfl_xor_sync(0xffffffffu, v, o));
    int wid = threadIdx.x >> 5;
    if ((threadIdx.x & 31) == 0) red[wid] = v;
    __syncthreads();
    if (threadIdx.x < 32) {
        float x = (threadIdx.x < 8) ? red[threadIdx.x] : -INFINITY;
#pragma unroll
        for (int o = 4; o; o >>= 1) x = fmaxf(x, __shfl_xor_sync(0xffffffffu, x, o));
        if (threadIdx.x == 0) red[0] = x;
    }
    __syncthreads();
    v = red[0];
    __syncthreads();
    return v;
}

__device__ __forceinline__ float blockSum(float v, float* red) {
#pragma unroll
    for (int o = 16; o; o >>= 1) v += __shfl_xor_sync(0xffffffffu, v, o);
    int wid = threadIdx.x >> 5;
    if ((threadIdx.x & 31) == 0) red[wid] = v;
    __syncthreads();
    if (threadIdx.x < 32) {
        float x = (threadIdx.x < 8) ? red[threadIdx.x] : 0.f;
#pragma unroll
        for (int o = 4; o; o >>= 1) x += __shfl_xor_sync(0xffffffffu, x, o);
        if (threadIdx.x == 0) red[0] = x;
    }
    __syncthreads();
    v = red[0];
    __syncthreads();
    return v;
}

// ---------- kernel 1: logits[b,k] ----------
// live: live_ll - 0.5*||x - xt||^2 / ts^2 - log(ts); new: ll (exact cancellation)
__global__ void k_logits(const float* __restrict__ xt,
                         const float* __restrict__ live_x0,
                         const float* __restrict__ live_ll,
                         const float* __restrict__ x0,
                         const float* __restrict__ ll,
                         const float* __restrict__ tsp) {
    int gw = (blockIdx.x * blockDim.x + threadIdx.x) >> 5;
    int lane = threadIdx.x & 31;
    if (gw >= BB * KC) return;
    int b = gw / KC;
    int k = gw - b * KC;
    if (k >= NL) {
        if (lane == 0) g_logits[gw] = ll[b * KN + (k - NL)];
        return;
    }
    const float4* xr  = (const float4*)(live_x0 + ((size_t)b * NL + k) * DD);
    const float4* xtr = (const float4*)(xt + (size_t)b * DD);
    float s = 0.f;
#pragma unroll
    for (int i = 0; i < 2; i++) {
        float4 a = xr[lane + i * 32];
        float4 c = xtr[lane + i * 32];
        float d0 = a.x - c.x, d1 = a.y - c.y, d2 = a.z - c.z, d3 = a.w - c.w;
        s += d0 * d0 + d1 * d1 + d2 * d2 + d3 * d3;
    }
#pragma unroll
    for (int o = 16; o; o >>= 1) s += __shfl_xor_sync(0xffffffffu, s, o);
    if (lane == 0) {
        float ts = *tsp;
        g_logits[gw] = live_ll[(size_t)b * NL + k] - 0.5f * s / (ts * ts) - logf(ts);
    }
}

// ---------- kernel 2: bootstrap samples + final score (grid = [NS+1, B]) ----------
// n < NS: bootstrap sample n. n == NS: final score (implicit cnt=1 everywhere).
__global__ void k_boot(const float* __restrict__ xt,
                       const float* __restrict__ live_x0,
                       const float* __restrict__ x0,
                       const int* __restrict__ bidx,
                       const float* __restrict__ tsp,
                       float* __restrict__ out) {
    extern __shared__ char smraw[];
    float* Lw  = (float*)smraw;             // KC: logits, then weights in place
    int*   cnt = (int*)(smraw + KC * 4);    // KC counts
    __shared__ float red[8];
    __shared__ int nact;
    __shared__ int   klist[LISTCAP];
    __shared__ float wlist[LISTCAP];
    int n = blockIdx.x, b = blockIdx.y, t = threadIdx.x;
    bool is_score = (n == NS);
    const float* L = g_logits + (size_t)b * KC;

    for (int k = t; k < KC; k += DD) { Lw[k] = L[k]; cnt[k] = 0; }
    if (t == 0) nact = 0;
    __syncthreads();

    // histogram + fused max over counted entries
    float m = -INFINITY;
    if (!is_score) {
        const int* idx = bidx + ((size_t)n * BB + b) * KC;
        for (int i = t; i < KC; i += DD) {
            int j = idx[i];
            atomicAdd(&cnt[j], 1);
            m = fmaxf(m, Lw[j]);
        }
    } else {
        for (int k = t; k < KC; k += DD) m = fmaxf(m, Lw[k]);
    }
    m = blockMax(m, red);

    // weights: expf only where it can be nonzero (exact: f32 expf underflows to 0 below ~-104)
    float z = 0.f;
    for (int k = t; k < KC; k += DD) {
        int c = is_score ? 1 : cnt[k];
        float l = Lw[k];
        float w = 0.f;
        if (c && (l - m > -100.f)) {
            w = (float)c * expf(l - m);
            int p = atomicAdd(&nact, 1);
            if (p < LISTCAP) { klist[p] = k; wlist[p] = w; }
        }
        Lw[k] = w;
        z += w;
    }
    z = blockSum(z, red);  // ends with __syncthreads -> list visible

    int na = nact;
    float ts = *tsp;
    float inv = 1.f / (z * ts);
    float acc = 0.f;
    if (na <= LISTCAP) {
        for (int j = 0; j < na; j++) {
            int k = klist[j];
            const float* row = (k < NL) ? (live_x0 + ((size_t)b * NL + k) * DD)
                                        : (x0 + ((size_t)b * KN + (k - NL)) * DD);
            acc = fmaf(wlist[j], row[t], acc);
        }
    } else {  // correctness fallback (never hit with this data)
        for (int k = 0; k < KC; k++) {
            float wv = Lw[k];
            if (wv != 0.f) {
                const float* row = (k < NL) ? (live_x0 + ((size_t)b * NL + k) * DD)
                                            : (x0 + ((size_t)b * KN + (k - NL)) * DD);
                acc = fmaf(wv, row[t], acc);
            }
        }
    }
    float val = acc * inv - xt[(size_t)b * DD + t] / ts;
    if (is_score) out[(size_t)b * DD + t] = val;
    else          g_boot[((size_t)n * BB + b) * DD + t] = val;
}

// ---------- kernel 3: std (ddof=1, double accum single pass) + converged ----------
__global__ void k_conv(const float* __restrict__ tsp, float* __restrict__ out, int out_size) {
    int b = blockIdx.x, d = threadIdx.x;
    float ts = *tsp;
    double s = 0.0, q = 0.0;
#pragma unroll 4
    for (int n = 0; n < NS; n++) {
        float x = g_boot[((size_t)n * BB + b) * DD + d];
        s += (double)x;
        q = fma((double)x, (double)x, q);
    }
    double mean = s * (1.0 / NS);
    double var = (q - s * mean) * (1.0 / (NS - 1));
    if (var < 0.0) var = 0.0;
    float sigma = sqrtf((float)var);
    int ok = sigma < 0.1f * ts;
    int all = __syncthreads_and(ok);
    if (d == 0 && out_size >= BB * DD + BB) out[BB * DD + b] = all ? 1.f : 0.f;
}

extern "C" void kernel_launch(void* const* d_in, const int* in_sizes, int n_in,
                              void* d_out, int out_size) {
    const float* xt      = (const float*)d_in[0];
    const float* live_x0 = (const float*)d_in[1];
    const float* live_ll = (const float*)d_in[2];
    const float* x0      = (const float*)d_in[3];
    const float* ll      = (const float*)d_in[4];
    const float* tsp     = (const float*)d_in[5];
    const int*   bidx    = (const int*)d_in[6];
    float* out = (float*)d_out;

    const int smem = KC * 8;  // 80256 B: logits/weights + counts
    cudaFuncSetAttribute(k_boot, cudaFuncAttributeMaxDynamicSharedMemorySize, smem);

    // 1 warp per (b,k) row
    k_logits<<<(BB * KC + 7) / 8, 256>>>(xt, live_x0, live_ll, x0, ll, tsp);

    dim3 g2(NS + 1, BB);
    k_boot<<<g2, 256, smem>>>(xt, live_x0, x0, bidx, tsp, out);

    k_conv<<<BB, 256>>>(tsp, out, out_size);
}

// round 3
// speedup vs baseline: 1.3406x; 1.3406x over previous
#include <cuda_runtime.h>
#include <math.h>

#define BB 8
#define DD 256
#define NL 10000
#define KN 32
#define KC 10032
#define NS 100
#define ACAP 120   // max active slots in int8 map

// scratch (no allocations allowed)
__device__ float g_logits[BB * KC];
__device__ float g_boot[NS * BB * DD];
__device__ signed char g_map[BB * KC];     // slot index or -1
__device__ int   g_actK[BB * 128];
__device__ float g_actL[BB * 128];
__device__ int   g_nact[BB];
__device__ float g_M[BB];

// ---------- block reductions (256 threads) ----------
__device__ __forceinline__ float blockMax(float v, float* red) {
#pragma unroll
    for (int o = 16; o; o >>= 1) v = fmaxf(v, __shfl_xor_sync(0xffffffffu, v, o));
    int wid = threadIdx.x >> 5;
    if ((threadIdx.x & 31) == 0) red[wid] = v;
    __syncthreads();
    if (threadIdx.x < 32) {
        float x = (threadIdx.x < 8) ? red[threadIdx.x] : -INFINITY;
#pragma unroll
        for (int o = 4; o; o >>= 1) x = fmaxf(x, __shfl_xor_sync(0xffffffffu, x, o));
        if (threadIdx.x == 0) red[0] = x;
    }
    __syncthreads();
    v = red[0];
    __syncthreads();
    return v;
}

__device__ __forceinline__ float blockSum(float v, float* red) {
#pragma unroll
    for (int o = 16; o; o >>= 1) v += __shfl_xor_sync(0xffffffffu, v, o);
    int wid = threadIdx.x >> 5;
    if ((threadIdx.x & 31) == 0) red[wid] = v;
    __syncthreads();
    if (threadIdx.x < 32) {
        float x = (threadIdx.x < 8) ? red[threadIdx.x] : 0.f;
#pragma unroll
        for (int o = 4; o; o >>= 1) x += __shfl_xor_sync(0xffffffffu, x, o);
        if (threadIdx.x == 0) red[0] = x;
    }
    __syncthreads();
    v = red[0];
    __syncthreads();
    return v;
}

__device__ __forceinline__ float dsq(float4 a, float4 c) {
    float d0 = a.x - c.x, d1 = a.y - c.y, d2 = a.z - c.z, d3 = a.w - c.w;
    return d0 * d0 + d1 * d1 + d2 * d2 + d3 * d3;
}

// ---------- kernel 1: logits, 2 rows per warp for MLP ----------
__global__ void k_logits(const float* __restrict__ xt,
                         const float* __restrict__ live_x0,
                         const float* __restrict__ live_ll,
                         const float* __restrict__ x0,
                         const float* __restrict__ ll,
                         const float* __restrict__ tsp) {
    int p = (blockIdx.x * blockDim.x + threadIdx.x) >> 5;  // pair id
    int lane = threadIdx.x & 31;
    const int PPB = KC / 2;  // 5016 pairs per b
    if (p >= BB * PPB) return;
    int b = p / PPB;
    int k0 = (p - b * PPB) * 2;
    if (k0 >= NL) {  // both rows are new particles: logits = ll exactly
        if (lane < 2) g_logits[(size_t)b * KC + k0 + lane] = ll[b * KN + (k0 - NL) + lane];
        return;
    }
    const float4* r0  = (const float4*)(live_x0 + ((size_t)b * NL + k0) * DD);
    const float4* r1  = r0 + (DD / 4);
    const float4* xtr = (const float4*)(xt + (size_t)b * DD);
    float4 c0 = xtr[lane], c1 = xtr[lane + 32];
    float4 a0 = r0[lane], a1 = r0[lane + 32];
    float4 b0 = r1[lane], b1 = r1[lane + 32];
    float s0 = dsq(a0, c0) + dsq(a1, c1);
    float s1 = dsq(b0, c0) + dsq(b1, c1);
#pragma unroll
    for (int o = 16; o; o >>= 1) {
        s0 += __shfl_xor_sync(0xffffffffu, s0, o);
        s1 += __shfl_xor_sync(0xffffffffu, s1, o);
    }
    if (lane == 0) {
        float ts = *tsp;
        float inv2 = 0.5f / (ts * ts), lg = logf(ts);
        size_t base = (size_t)b * KC + k0;
        g_logits[base]     = live_ll[(size_t)b * NL + k0]     - s0 * inv2 - lg;
        g_logits[base + 1] = live_ll[(size_t)b * NL + k0 + 1] - s1 * inv2 - lg;
    }
}

// ---------- kernel 2: per-b global max + active set + int8 map ----------
__global__ void k_active() {
    __shared__ float red[8];
    __shared__ int na;
    int b = blockIdx.x, t = threadIdx.x;
    const float* L = g_logits + (size_t)b * KC;
    float m = -INFINITY;
    for (int k = t; k < KC; k += 256) m = fmaxf(m, L[k]);
    m = blockMax(m, red);
    if (t == 0) { g_M[b] = m; na = 0; }
    __syncthreads();
    float thr = m - 120.f;
    for (int k = t; k < KC; k += 256) {
        float l = L[k];
        int s = -1;
        if (l > thr) {
            int q = atomicAdd(&na, 1);
            if (q < ACAP) { g_actK[b * 128 + q] = k; g_actL[b * 128 + q] = l; s = q; }
        }
        g_map[(size_t)b * KC + k] = (signed char)s;
    }
    __syncthreads();
    if (t == 0) g_nact[b] = na;
}

// ---------- kernel 3: bootstrap + final score (grid = [NS+1, B]) ----------
__global__ void k_boot(const float* __restrict__ xt,
                       const float* __restrict__ live_x0,
                       const float* __restrict__ x0,
                       const int* __restrict__ bidx,
                       const float* __restrict__ tsp,
                       float* __restrict__ out) {
    __shared__ signed char map[KC + 16];
    __shared__ int cnt[128];
    __shared__ int actK[128];
    __shared__ float actL[128];
    __shared__ float warr[128];
    __shared__ float red[8];
    int n = blockIdx.x, b = blockIdx.y, t = threadIdx.x;
    bool is_score = (n == NS);
    int na = g_nact[b];
    float M = g_M[b];
    const int* idx = bidx + ((size_t)n * BB + b) * KC;

    if (t < 128) {
        cnt[t] = (is_score && t < na) ? 1 : 0;
        warr[t] = 0.f;
        if (t < na && na <= ACAP) { actK[t] = g_actK[b * 128 + t]; actL[t] = g_actL[b * 128 + t]; }
    }
    if (!is_score) {  // copy int8 map to smem (KC divisible by 16)
        const uint4* src = (const uint4*)(g_map + (size_t)b * KC);
        uint4* dst = (uint4*)map;
        for (int i = t; i < KC / 16; i += 256) dst[i] = src[i];
    }
    __syncthreads();

    if (!is_score) {
        for (int i = t; i < KC; i += 256) {
            int j = idx[i];
            int s = map[j];
            if (s >= 0) atomicAdd(&cnt[s], 1);
        }
        __syncthreads();
    }

    float v = (t < 128 && t < na && cnt[t] > 0) ? actL[t] : -INFINITY;
    float m = blockMax(v, red);

    float ts = *tsp;
    bool fast = (na >= 1 && na <= ACAP && m > M - 16.f);

    float acc = 0.f, z;
    if (fast) {
        float w = 0.f;
        if (t < 128 && t < na && cnt[t] > 0) w = (float)cnt[t] * expf(actL[t] - m);
        if (t < 128) warr[t] = w;
        z = blockSum(w, red);  // ends with syncthreads -> warr visible

        int j = 0;
        for (; j + 3 < na; j += 4) {
            float w0 = warr[j], w1 = warr[j + 1], w2 = warr[j + 2], w3 = warr[j + 3];
            int k0 = actK[j], k1 = actK[j + 1], k2 = actK[j + 2], k3 = actK[j + 3];
            const float* r0 = (k0 < NL) ? live_x0 + ((size_t)b * NL + k0) * DD : x0 + ((size_t)b * KN + (k0 - NL)) * DD;
            const float* r1 = (k1 < NL) ? live_x0 + ((size_t)b * NL + k1) * DD : x0 + ((size_t)b * KN + (k1 - NL)) * DD;
            const float* r2 = (k2 < NL) ? live_x0 + ((size_t)b * NL + k2) * DD : x0 + ((size_t)b * KN + (k2 - NL)) * DD;
            const float* r3 = (k3 < NL) ? live_x0 + ((size_t)b * NL + k3) * DD : x0 + ((size_t)b * KN + (k3 - NL)) * DD;
            float v0 = (w0 != 0.f) ? r0[t] : 0.f;
            float v1 = (w1 != 0.f) ? r1[t] : 0.f;
            float v2 = (w2 != 0.f) ? r2[t] : 0.f;
            float v3 = (w3 != 0.f) ? r3[t] : 0.f;
            acc = fmaf(w0, v0, acc); acc = fmaf(w1, v1, acc);
            acc = fmaf(w2, v2, acc); acc = fmaf(w3, v3, acc);
        }
        for (; j < na; j++) {
            float wj = warr[j];
            if (wj != 0.f) {
                int k = actK[j];
                const float* r = (k < NL) ? live_x0 + ((size_t)b * NL + k) * DD : x0 + ((size_t)b * KN + (k - NL)) * DD;
                acc = fmaf(wj, r[t], acc);
            }
        }
    } else {
        // exact slow path (never taken with this data)
        const float* L = g_logits + (size_t)b * KC;
        float mm = -INFINITY;
        if (is_score) { for (int k = t; k < KC; k += 256) mm = fmaxf(mm, L[k]); }
        else          { for (int i = t; i < KC; i += 256) mm = fmaxf(mm, L[idx[i]]); }
        mm = blockMax(mm, red);
        float zz = 0.f;
        if (is_score) { for (int k = t; k < KC; k += 256) zz += expf(L[k] - mm); }
        else          { for (int i = t; i < KC; i += 256) zz += expf(L[idx[i]] - mm); }
        z = blockSum(zz, red);
        for (int i = 0; i < KC; i++) {
            int k = is_score ? i : idx[i];
            float w = expf(L[k] - mm);
            if (w != 0.f) {
                const float* r = (k < NL) ? live_x0 + ((size_t)b * NL + k) * DD : x0 + ((size_t)b * KN + (k - NL)) * DD;
                acc = fmaf(w, r[t], acc);
            }
        }
    }

    float val = acc / (z * ts) - xt[(size_t)b * DD + t] / ts;
    if (is_score) out[(size_t)b * DD + t] = val;
    else          g_boot[((size_t)n * BB + b) * DD + t] = val;
}

// ---------- kernel 4: std (ddof=1) + converged ----------
__global__ void k_conv(const float* __restrict__ tsp, float* __restrict__ out, int out_size) {
    int b = blockIdx.x, d = threadIdx.x;
    float ts = *tsp;
    double s = 0.0, q = 0.0;
#pragma unroll 10
    for (int n = 0; n < NS; n++) {
        float x = g_boot[((size_t)n * BB + b) * DD + d];
        s += (double)x;
        q = fma((double)x, (double)x, q);
    }
    double mean = s * (1.0 / NS);
    double var = (q - s * mean) * (1.0 / (NS - 1));
    if (var < 0.0) var = 0.0;
    float sigma = sqrtf((float)var);
    int ok = sigma < 0.1f * ts;
    int all = __syncthreads_and(ok);
    if (d == 0 && out_size >= BB * DD + BB) out[BB * DD + b] = all ? 1.f : 0.f;
}

extern "C" void kernel_launch(void* const* d_in, const int* in_sizes, int n_in,
                              void* d_out, int out_size) {
    const float* xt      = (const float*)d_in[0];
    const float* live_x0 = (const float*)d_in[1];
    const float* live_ll = (const float*)d_in[2];
    const float* x0      = (const float*)d_in[3];
    const float* ll      = (const float*)d_in[4];
    const float* tsp     = (const float*)d_in[5];
    const int*   bidx    = (const int*)d_in[6];
    float* out = (float*)d_out;

    // 2 rows per warp: BB*KC/2 = 40128 pairs, 8 pairs/CTA
    k_logits<<<(BB * (KC / 2) + 7) / 8, 256>>>(xt, live_x0, live_ll, x0, ll, tsp);

    k_active<<<BB, 256>>>();

    dim3 g3(NS + 1, BB);
    k_boot<<<g3, 256>>>(xt, live_x0, x0, bidx, tsp, out);

    k_conv<<<BB, 256>>>(tsp, out, out_size);
}

// round 5
// speedup vs baseline: 1.7829x; 1.3299x over previous
#include <cuda_runtime.h>
#include <math.h>

#define BB 8
#define DD 256
#define NL 10000
#define KN 32
#define KC 10032
#define NS 100
#define ACAP 120   // max active slots in int8 map

// scratch (no allocations allowed)
__device__ float g_logits[BB * KC];
__device__ float g_bootT[BB * DD * NS];    // transposed: [(b*DD+d)*NS + n]
__device__ signed char g_map[BB * KC];     // slot index or -1
__device__ int   g_actK[BB * 128];
__device__ float g_actL[BB * 128];
__device__ int   g_nact[BB];
__device__ float g_M[BB];
__device__ int   g_flag[BB];

// ---------- block reductions (256 threads) ----------
__device__ __forceinline__ float blockMax(float v, float* red) {
#pragma unroll
    for (int o = 16; o; o >>= 1) v = fmaxf(v, __shfl_xor_sync(0xffffffffu, v, o));
    int wid = threadIdx.x >> 5;
    if ((threadIdx.x & 31) == 0) red[wid] = v;
    __syncthreads();
    if (threadIdx.x < 32) {
        float x = (threadIdx.x < 8) ? red[threadIdx.x] : -INFINITY;
#pragma unroll
        for (int o = 4; o; o >>= 1) x = fmaxf(x, __shfl_xor_sync(0xffffffffu, x, o));
        if (threadIdx.x == 0) red[0] = x;
    }
    __syncthreads();
    v = red[0];
    __syncthreads();
    return v;
}

__device__ __forceinline__ float blockSum(float v, float* red) {
#pragma unroll
    for (int o = 16; o; o >>= 1) v += __shfl_xor_sync(0xffffffffu, v, o);
    int wid = threadIdx.x >> 5;
    if ((threadIdx.x & 31) == 0) red[wid] = v;
    __syncthreads();
    if (threadIdx.x < 32) {
        float x = (threadIdx.x < 8) ? red[threadIdx.x] : 0.f;
#pragma unroll
        for (int o = 4; o; o >>= 1) x += __shfl_xor_sync(0xffffffffu, x, o);
        if (threadIdx.x == 0) red[0] = x;
    }
    __syncthreads();
    v = red[0];
    __syncthreads();
    return v;
}

__device__ __forceinline__ float dsq(float4 a, float4 c) {
    float d0 = a.x - c.x, d1 = a.y - c.y, d2 = a.z - c.z, d3 = a.w - c.w;
    return d0 * d0 + d1 * d1 + d2 * d2 + d3 * d3;
}

// ---------- kernel 1: logits, 4 rows per warp for MLP ----------
// NL = 10000 divisible by 4 -> a quad is fully live or fully new.
__global__ void k_logits(const float* __restrict__ xt,
                         const float* __restrict__ live_x0,
                         const float* __restrict__ live_ll,
                         const float* __restrict__ x0,
                         const float* __restrict__ ll,
                         const float* __restrict__ tsp) {
    int q = (blockIdx.x * blockDim.x + threadIdx.x) >> 5;  // quad id
    int lane = threadIdx.x & 31;
    const int QPB = KC / 4;  // 2508
    if (q >= BB * QPB) return;
    int b = q / QPB;
    int k0 = (q - b * QPB) * 4;
    if (k0 >= NL) {  // all 4 new particles: logits = ll exactly
        if (lane < 4) g_logits[(size_t)b * KC + k0 + lane] = ll[b * KN + (k0 - NL) + lane];
        return;
    }
    const float4* r0 = (const float4*)(live_x0 + ((size_t)b * NL + k0) * DD);
    const float4* r1 = r0 + (DD / 4);
    const float4* r2 = r1 + (DD / 4);
    const float4* r3 = r2 + (DD / 4);
    const float4* xtr = (const float4*)(xt + (size_t)b * DD);
    float4 c0 = xtr[lane], c1 = xtr[lane + 32];
    float4 a00 = r0[lane], a01 = r0[lane + 32];
    float4 a10 = r1[lane], a11 = r1[lane + 32];
    float4 a20 = r2[lane], a21 = r2[lane + 32];
    float4 a30 = r3[lane], a31 = r3[lane + 32];
    float s0 = dsq(a00, c0) + dsq(a01, c1);
    float s1 = dsq(a10, c0) + dsq(a11, c1);
    float s2 = dsq(a20, c0) + dsq(a21, c1);
    float s3 = dsq(a30, c0) + dsq(a31, c1);
#pragma unroll
    for (int o = 16; o; o >>= 1) {
        s0 += __shfl_xor_sync(0xffffffffu, s0, o);
        s1 += __shfl_xor_sync(0xffffffffu, s1, o);
        s2 += __shfl_xor_sync(0xffffffffu, s2, o);
        s3 += __shfl_xor_sync(0xffffffffu, s3, o);
    }
    if (lane == 0) {
        float ts = *tsp;
        float inv2 = 0.5f / (ts * ts), lg = logf(ts);
        size_t base = (size_t)b * KC + k0;
        const float* lr = live_ll + (size_t)b * NL + k0;
        g_logits[base]     = lr[0] - s0 * inv2 - lg;
        g_logits[base + 1] = lr[1] - s1 * inv2 - lg;
        g_logits[base + 2] = lr[2] - s2 * inv2 - lg;
        g_logits[base + 3] = lr[3] - s3 * inv2 - lg;
    }
}

// ---------- kernel 2: per-b global max + active set + int8 map ----------
__global__ void k_active() {
    __shared__ float red[8];
    __shared__ int na;
    int b = blockIdx.x, t = threadIdx.x;
    const float* L = g_logits + (size_t)b * KC;
    float m = -INFINITY;
    for (int k = t; k < KC; k += 256) m = fmaxf(m, L[k]);
    m = blockMax(m, red);
    if (t == 0) { g_M[b] = m; na = 0; g_flag[b] = 1; }
    __syncthreads();
    float thr = m - 120.f;
    for (int k = t; k < KC; k += 256) {
        float l = L[k];
        int s = -1;
        if (l > thr) {
            int p = atomicAdd(&na, 1);
            if (p < ACAP) { g_actK[b * 128 + p] = k; g_actL[b * 128 + p] = l; s = p; }
        }
        g_map[(size_t)b * KC + k] = (signed char)s;
    }
    __syncthreads();
    if (t == 0) g_nact[b] = na;
}

// ---------- kernel 3: bootstrap + final score (grid = [NS+1, B]) ----------
__global__ void k_boot(const float* __restrict__ xt,
                       const float* __restrict__ live_x0,
                       const float* __restrict__ x0,
                       const int* __restrict__ bidx,
                       const float* __restrict__ tsp,
                       float* __restrict__ out) {
    __shared__ signed char map[KC + 16];
    __shared__ int cnt[128];
    __shared__ int actK[128];
    __shared__ float actL[128];
    __shared__ float warr[128];
    __shared__ float red[8];
    int n = blockIdx.x, b = blockIdx.y, t = threadIdx.x;
    bool is_score = (n == NS);
    int na = g_nact[b];
    float M = g_M[b];
    const int* idx = bidx + ((size_t)n * BB + b) * KC;

    if (t < 128) {
        cnt[t] = (is_score && t < na) ? 1 : 0;
        warr[t] = 0.f;
        if (t < na && na <= ACAP) { actK[t] = g_actK[b * 128 + t]; actL[t] = g_actL[b * 128 + t]; }
    }
    if (!is_score) {  // copy int8 map to smem
        const uint4* src = (const uint4*)(g_map + (size_t)b * KC);
        uint4* dst = (uint4*)map;
        for (int i = t; i < KC / 16; i += 256) dst[i] = src[i];
    }
    __syncthreads();

    if (!is_score) {
        for (int i = t; i < KC; i += 256) {
            int s = map[idx[i]];
            if (s >= 0) atomicAdd(&cnt[s], 1);
        }
        __syncthreads();
    }

    float v = (t < 128 && t < na && cnt[t] > 0) ? actL[t] : -INFINITY;
    float m = blockMax(v, red);

    float ts = *tsp;
    bool fast = (na >= 1 && na <= ACAP && m > M - 16.f);

    float acc = 0.f, z;
    if (fast) {
        float w = 0.f;
        if (t < 128 && t < na && cnt[t] > 0) w = (float)cnt[t] * expf(actL[t] - m);
        if (t < 128) warr[t] = w;
        z = blockSum(w, red);

        int j = 0;
        for (; j + 3 < na; j += 4) {
            float w0 = warr[j], w1 = warr[j + 1], w2 = warr[j + 2], w3 = warr[j + 3];
            int k0 = actK[j], k1 = actK[j + 1], k2 = actK[j + 2], k3 = actK[j + 3];
            const float* r0 = (k0 < NL) ? live_x0 + ((size_t)b * NL + k0) * DD : x0 + ((size_t)b * KN + (k0 - NL)) * DD;
            const float* r1 = (k1 < NL) ? live_x0 + ((size_t)b * NL + k1) * DD : x0 + ((size_t)b * KN + (k1 - NL)) * DD;
            const float* r2 = (k2 < NL) ? live_x0 + ((size_t)b * NL + k2) * DD : x0 + ((size_t)b * KN + (k2 - NL)) * DD;
            const float* r3 = (k3 < NL) ? live_x0 + ((size_t)b * NL + k3) * DD : x0 + ((size_t)b * KN + (k3 - NL)) * DD;
            float v0 = (w0 != 0.f) ? r0[t] : 0.f;
            float v1 = (w1 != 0.f) ? r1[t] : 0.f;
            float v2 = (w2 != 0.f) ? r2[t] : 0.f;
            float v3 = (w3 != 0.f) ? r3[t] : 0.f;
            acc = fmaf(w0, v0, acc); acc = fmaf(w1, v1, acc);
            acc = fmaf(w2, v2, acc); acc = fmaf(w3, v3, acc);
        }
        for (; j < na; j++) {
            float wj = warr[j];
            if (wj != 0.f) {
                int k = actK[j];
                const float* r = (k < NL) ? live_x0 + ((size_t)b * NL + k) * DD : x0 + ((size_t)b * KN + (k - NL)) * DD;
                acc = fmaf(wj, r[t], acc);
            }
        }
    } else {
        // exact slow path (never taken with this data)
        const float* L = g_logits + (size_t)b * KC;
        float mm = -INFINITY;
        if (is_score) { for (int k = t; k < KC; k += 256) mm = fmaxf(mm, L[k]); }
        else          { for (int i = t; i < KC; i += 256) mm = fmaxf(mm, L[idx[i]]); }
        mm = blockMax(mm, red);
        float zz = 0.f;
        if (is_score) { for (int k = t; k < KC; k += 256) zz += expf(L[k] - mm); }
        else          { for (int i = t; i < KC; i += 256) zz += expf(L[idx[i]] - mm); }
        z = blockSum(zz, red);
        for (int i = 0; i < KC; i++) {
            int k = is_score ? i : idx[i];
            float w = expf(L[k] - mm);
            if (w != 0.f) {
                const float* r = (k < NL) ? live_x0 + ((size_t)b * NL + k) * DD : x0 + ((size_t)b * KN + (k - NL)) * DD;
                acc = fmaf(w, r[t], acc);
            }
        }
    }

    float val = acc / (z * ts) - xt[(size_t)b * DD + t] / ts;
    if (is_score) out[(size_t)b * DD + t] = val;
    else          g_bootT[((size_t)b * DD + t) * NS + n] = val;
}

// ---------- kernel 4: warp per (b,d): two-pass std (ddof=1) ----------
// grid = 256 CTAs x 256 threads -> 2048 warps = BB*DD
__global__ void k_conv(const float* __restrict__ tsp) {
    int W = blockIdx.x * 8 + (threadIdx.x >> 5);
    int lane = threadIdx.x & 31;
    int b = W >> 8;
    const float* p = g_bootT + (size_t)W * NS;
    float x0 = p[lane];
    float x1 = p[lane + 32];
    float x2 = p[lane + 64];
    float x3 = (lane < 4) ? p[lane + 96] : 0.f;
    float s = x0 + x1 + x2 + x3;
#pragma unroll
    for (int o = 16; o; o >>= 1) s += __shfl_xor_sync(0xffffffffu, s, o);
    float mean = s * (1.f / NS);
    float d0 = x0 - mean, d1 = x1 - mean, d2 = x2 - mean;
    float d3 = (lane < 4) ? (x3 - mean) : 0.f;
    float ss = d0 * d0 + d1 * d1 + d2 * d2 + d3 * d3;
#pragma unroll
    for (int o = 16; o; o >>= 1) ss += __shfl_xor_sync(0xffffffffu, ss, o);
    if (lane == 0) {
        float sigma = sqrtf(ss * (1.f / (NS - 1)));
        if (!(sigma < 0.1f * (*tsp))) atomicAnd(&g_flag[b], 0);
    }
}

// ---------- kernel 5: emit converged flags ----------
__global__ void k_flag(float* __restrict__ out, int out_size) {
    int t = threadIdx.x;
    if (t < BB && out_size >= BB * DD + BB) out[BB * DD + t] = g_flag[t] ? 1.f : 0.f;
}

extern "C" void kernel_launch(void* const* d_in, const int* in_sizes, int n_in,
                              void* d_out, int out_size) {
    const float* xt      = (const float*)d_in[0];
    const float* live_x0 = (const float*)d_in[1];
    const float* live_ll = (const float*)d_in[2];
    const float* x0      = (const float*)d_in[3];
    const float* ll      = (const float*)d_in[4];
    const float* tsp     = (const float*)d_in[5];
    const int*   bidx    = (const int*)d_in[6];
    float* out = (float*)d_out;

    // 4 rows per warp: BB*KC/4 = 20064 quads, 8 per CTA
    k_logits<<<(BB * (KC / 4) + 7) / 8, 256>>>(xt, live_x0, live_ll, x0, ll, tsp);

    k_active<<<BB, 256>>>();

    dim3 g3(NS + 1, BB);
    k_boot<<<g3, 256>>>(xt, live_x0, x0, bidx, tsp, out);

    k_conv<<<256, 256>>>(tsp);
    k_flag<<<1, 32>>>(out, out_size);
}

// round 6
// speedup vs baseline: 1.8798x; 1.0543x over previous
#include <cuda_runtime.h>
#include <math.h>

#define BB 8
#define DD 256
#define NL 10000
#define KN 32
#define KC 10032
#define NS 100
#define ACAP 120

#define HISTB (NS * BB)            // 800 histogram CTAs
#define QPB   (KC / 4)             // 2508 quads per b
#define LOGB  (BB * QPB / 8)       // 2508 logits CTAs (8 quads each)
#define TOTB  (HISTB + LOGB)

// scratch (no allocations allowed)
__device__ float g_logits[BB * KC];
__device__ float g_bootT[BB * DD * NS];   // [(b*DD+d)*NS + n]
__device__ int   g_cnt[NS * BB * 32];     // per-sample counts of new-particle hits
__device__ int   g_actK[BB * 128];
__device__ float g_actL[BB * 128];
__device__ int   g_nact[BB];
__device__ float g_M[BB];
__device__ int   g_allnew[BB];
__device__ int   g_flag[BB];
__device__ int   g_done  = 0;
__device__ int   g_done2 = 0;
__device__ int   g_done3 = 0;

// ---------- block reductions (256 threads) ----------
__device__ __forceinline__ float blockMax(float v, float* red) {
#pragma unroll
    for (int o = 16; o; o >>= 1) v = fmaxf(v, __shfl_xor_sync(0xffffffffu, v, o));
    int wid = threadIdx.x >> 5;
    if ((threadIdx.x & 31) == 0) red[wid] = v;
    __syncthreads();
    if (threadIdx.x < 32) {
        float x = (threadIdx.x < 8) ? red[threadIdx.x] : -INFINITY;
#pragma unroll
        for (int o = 4; o; o >>= 1) x = fmaxf(x, __shfl_xor_sync(0xffffffffu, x, o));
        if (threadIdx.x == 0) red[0] = x;
    }
    __syncthreads();
    v = red[0];
    __syncthreads();
    return v;
}

__device__ __forceinline__ float blockSum(float v, float* red) {
#pragma unroll
    for (int o = 16; o; o >>= 1) v += __shfl_xor_sync(0xffffffffu, v, o);
    int wid = threadIdx.x >> 5;
    if ((threadIdx.x & 31) == 0) red[wid] = v;
    __syncthreads();
    if (threadIdx.x < 32) {
        float x = (threadIdx.x < 8) ? red[threadIdx.x] : 0.f;
#pragma unroll
        for (int o = 4; o; o >>= 1) x += __shfl_xor_sync(0xffffffffu, x, o);
        if (threadIdx.x == 0) red[0] = x;
    }
    __syncthreads();
    v = red[0];
    __syncthreads();
    return v;
}

__device__ __forceinline__ float dsq(float4 a, float4 c) {
    float d0 = a.x - c.x, d1 = a.y - c.y, d2 = a.z - c.z, d3 = a.w - c.w;
    return d0 * d0 + d1 * d1 + d2 * d2 + d3 * d3;
}

// ---------- kernel 1: fused logits + new-range histogram + active-set tail ----------
__global__ void k_fused(const float* __restrict__ xt,
                        const float* __restrict__ live_x0,
                        const float* __restrict__ live_ll,
                        const float* __restrict__ x0,
                        const float* __restrict__ ll,
                        const float* __restrict__ tsp,
                        const int* __restrict__ bidx) {
    __shared__ float red[8];
    __shared__ int cnt32[32];
    __shared__ int sh_na, sh_ticket;
    __shared__ int   sK[ACAP];
    __shared__ float sL[ACAP];
    int bid = blockIdx.x, t = threadIdx.x;

    if (bid < HISTB) {
        // ---- histogram of idx over the new-particle range [NL, KC) ----
        int n = bid >> 3, b = bid & 7;
        if (t < 32) cnt32[t] = 0;
        __syncthreads();
        const uint4* src = (const uint4*)(bidx + ((size_t)n * BB + b) * KC);
        for (int i = t; i < KC / 4; i += 256) {
            uint4 v = src[i];
            int s0 = (int)v.x - NL, s1 = (int)v.y - NL;
            int s2 = (int)v.z - NL, s3 = (int)v.w - NL;
            if (s0 >= 0) atomicAdd(&cnt32[s0], 1);
            if (s1 >= 0) atomicAdd(&cnt32[s1], 1);
            if (s2 >= 0) atomicAdd(&cnt32[s2], 1);
            if (s3 >= 0) atomicAdd(&cnt32[s3], 1);
        }
        __syncthreads();
        if (t < 32) g_cnt[((size_t)n * BB + b) * 32 + t] = cnt32[t];
    } else {
        // ---- logits: 4 rows per warp ----
        int q = (bid - HISTB) * 8 + (t >> 5);
        int lane = t & 31;
        int b = q / QPB;
        int k0 = (q - b * QPB) * 4;
        if (k0 >= NL) {
            if (lane < 4) g_logits[(size_t)b * KC + k0 + lane] = ll[b * KN + (k0 - NL) + lane];
        } else {
            const float4* r0 = (const float4*)(live_x0 + ((size_t)b * NL + k0) * DD);
            const float4* r1 = r0 + (DD / 4);
            const float4* r2 = r1 + (DD / 4);
            const float4* r3 = r2 + (DD / 4);
            const float4* xtr = (const float4*)(xt + (size_t)b * DD);
            float4 c0 = xtr[lane], c1 = xtr[lane + 32];
            float4 a00 = r0[lane], a01 = r0[lane + 32];
            float4 a10 = r1[lane], a11 = r1[lane + 32];
            float4 a20 = r2[lane], a21 = r2[lane + 32];
            float4 a30 = r3[lane], a31 = r3[lane + 32];
            float s0 = dsq(a00, c0) + dsq(a01, c1);
            float s1 = dsq(a10, c0) + dsq(a11, c1);
            float s2 = dsq(a20, c0) + dsq(a21, c1);
            float s3 = dsq(a30, c0) + dsq(a31, c1);
#pragma unroll
            for (int o = 16; o; o >>= 1) {
                s0 += __shfl_xor_sync(0xffffffffu, s0, o);
                s1 += __shfl_xor_sync(0xffffffffu, s1, o);
                s2 += __shfl_xor_sync(0xffffffffu, s2, o);
                s3 += __shfl_xor_sync(0xffffffffu, s3, o);
            }
            if (lane == 0) {
                float ts = *tsp;
                float inv2 = 0.5f / (ts * ts), lg = logf(ts);
                size_t base = (size_t)b * KC + k0;
                const float* lr = live_ll + (size_t)b * NL + k0;
                g_logits[base]     = lr[0] - s0 * inv2 - lg;
                g_logits[base + 1] = lr[1] - s1 * inv2 - lg;
                g_logits[base + 2] = lr[2] - s2 * inv2 - lg;
                g_logits[base + 3] = lr[3] - s3 * inv2 - lg;
            }
        }
    }

    // ---- tail: last 8 CTAs compute per-b active set ----
    __threadfence();
    __syncthreads();
    if (t == 0) sh_ticket = atomicAdd(&g_done, 1);
    __syncthreads();
    int ticket = sh_ticket;
    if (ticket >= TOTB - BB) {
        int b = ticket - (TOTB - BB);
        const float* L = g_logits + (size_t)b * KC;
        float m = -INFINITY;
        for (int k = t; k < KC; k += 256) m = fmaxf(m, L[k]);
        m = blockMax(m, red);
        if (t == 0) sh_na = 0;
        __syncthreads();
        float thr = m - 120.f;
        for (int k = t; k < KC; k += 256) {
            float l = L[k];
            if (l > thr) {
                int p = atomicAdd(&sh_na, 1);
                if (p < ACAP) { sK[p] = k; sL[p] = l; }
            }
        }
        __syncthreads();
        int na = sh_na;
        if (t == 0) {
            int lim = na < ACAP ? na : ACAP;
            // insertion sort by k (deterministic ordering)
            for (int i = 1; i < lim; i++) {
                int kk = sK[i]; float lv = sL[i];
                int j = i - 1;
                while (j >= 0 && sK[j] > kk) { sK[j + 1] = sK[j]; sL[j + 1] = sL[j]; j--; }
                sK[j + 1] = kk; sL[j + 1] = lv;
            }
            int allnew = 1;
            for (int i = 0; i < lim; i++) if (sK[i] < NL) allnew = 0;
            g_nact[b] = na;
            g_M[b] = m;
            g_allnew[b] = allnew;
            g_flag[b] = 1;
        }
        __syncthreads();
        if (t < na && t < ACAP) {
            g_actK[b * 128 + t] = sK[t];
            g_actL[b * 128 + t] = sL[t];
        }
        __threadfence();
        __syncthreads();
        if (t == 0) {
            int t2 = atomicAdd(&g_done2, 1);
            if (t2 == BB - 1) { g_done = 0; g_done2 = 0; }
        }
    }
}

// ---------- kernel 2: bootstrap + final score (grid = [NS+1, B]) ----------
__global__ void k_boot(const float* __restrict__ xt,
                       const float* __restrict__ live_x0,
                       const float* __restrict__ x0,
                       const int* __restrict__ bidx,
                       const float* __restrict__ tsp,
                       float* __restrict__ out) {
    __shared__ int   actK[128];
    __shared__ float actL[128];
    __shared__ int   cc[128];
    __shared__ float warr[128];
    __shared__ float red[8];
    int n = blockIdx.x, b = blockIdx.y, t = threadIdx.x;
    bool is_score = (n == NS);
    int na = g_nact[b];
    float M = g_M[b];
    int allnew = g_allnew[b];

    if (t < 128) {
        int c = 0;
        if (t < na && na <= ACAP) {
            int k = g_actK[b * 128 + t];
            actK[t] = k;
            actL[t] = g_actL[b * 128 + t];
            if (is_score) c = 1;
            else if (k >= NL) c = g_cnt[((size_t)n * BB + b) * 32 + (k - NL)];
        }
        cc[t] = c;
        warr[t] = 0.f;
    }
    __syncthreads();

    float v = (t < 128 && t < na && cc[t] > 0) ? actL[t] : -INFINITY;
    float m = blockMax(v, red);

    float ts = *tsp;
    bool fast = allnew && na >= 1 && na <= ACAP && (m > M - 16.f);

    float acc = 0.f, z;
    if (fast) {
        float w = 0.f;
        if (t < 128 && t < na && cc[t] > 0) w = (float)cc[t] * expf(actL[t] - m);
        if (t < 128) warr[t] = w;
        z = blockSum(w, red);  // ends with __syncthreads -> warr visible

        int j = 0;
        for (; j + 3 < na; j += 4) {
            float w0 = warr[j], w1 = warr[j + 1], w2 = warr[j + 2], w3 = warr[j + 3];
            int k0 = actK[j], k1 = actK[j + 1], k2 = actK[j + 2], k3 = actK[j + 3];
            const float* r0 = (k0 < NL) ? live_x0 + ((size_t)b * NL + k0) * DD : x0 + ((size_t)b * KN + (k0 - NL)) * DD;
            const float* r1 = (k1 < NL) ? live_x0 + ((size_t)b * NL + k1) * DD : x0 + ((size_t)b * KN + (k1 - NL)) * DD;
            const float* r2 = (k2 < NL) ? live_x0 + ((size_t)b * NL + k2) * DD : x0 + ((size_t)b * KN + (k2 - NL)) * DD;
            const float* r3 = (k3 < NL) ? live_x0 + ((size_t)b * NL + k3) * DD : x0 + ((size_t)b * KN + (k3 - NL)) * DD;
            float v0 = (w0 != 0.f) ? r0[t] : 0.f;
            float v1 = (w1 != 0.f) ? r1[t] : 0.f;
            float v2 = (w2 != 0.f) ? r2[t] : 0.f;
            float v3 = (w3 != 0.f) ? r3[t] : 0.f;
            acc = fmaf(w0, v0, acc); acc = fmaf(w1, v1, acc);
            acc = fmaf(w2, v2, acc); acc = fmaf(w3, v3, acc);
        }
        for (; j < na; j++) {
            float wj = warr[j];
            if (wj != 0.f) {
                int k = actK[j];
                const float* r = (k < NL) ? live_x0 + ((size_t)b * NL + k) * DD : x0 + ((size_t)b * KN + (k - NL)) * DD;
                acc = fmaf(wj, r[t], acc);
            }
        }
    } else {
        // exact slow path (never taken with this data)
        const int* idx = bidx + ((size_t)n * BB + b) * KC;
        const float* L = g_logits + (size_t)b * KC;
        float mm = -INFINITY;
        if (is_score) { for (int k = t; k < KC; k += 256) mm = fmaxf(mm, L[k]); }
        else          { for (int i = t; i < KC; i += 256) mm = fmaxf(mm, L[idx[i]]); }
        mm = blockMax(mm, red);
        float zz = 0.f;
        if (is_score) { for (int k = t; k < KC; k += 256) zz += expf(L[k] - mm); }
        else          { for (int i = t; i < KC; i += 256) zz += expf(L[idx[i]] - mm); }
        z = blockSum(zz, red);
        for (int i = 0; i < KC; i++) {
            int k = is_score ? i : idx[i];
            float w = expf(L[k] - mm);
            if (w != 0.f) {
                const float* r = (k < NL) ? live_x0 + ((size_t)b * NL + k) * DD : x0 + ((size_t)b * KN + (k - NL)) * DD;
                acc = fmaf(w, r[t], acc);
            }
        }
    }

    float val = acc / (z * ts) - xt[(size_t)b * DD + t] / ts;
    if (is_score) out[(size_t)b * DD + t] = val;
    else          g_bootT[((size_t)b * DD + t) * NS + n] = val;
}

// ---------- kernel 3: warp per (b,d) std + fused flag emit ----------
__global__ void k_conv(const float* __restrict__ tsp, float* __restrict__ out, int out_size) {
    __shared__ int sh_ticket;
    int W = blockIdx.x * 8 + (threadIdx.x >> 5);
    int lane = threadIdx.x & 31;
    int b = W >> 8;
    const float* p = g_bootT + (size_t)W * NS;
    float x0 = p[lane];
    float x1 = p[lane + 32];
    float x2 = p[lane + 64];
    float x3 = (lane < 4) ? p[lane + 96] : 0.f;
    float s = x0 + x1 + x2 + x3;
#pragma unroll
    for (int o = 16; o; o >>= 1) s += __shfl_xor_sync(0xffffffffu, s, o);
    float mean = s * (1.f / NS);
    float d0 = x0 - mean, d1 = x1 - mean, d2 = x2 - mean;
    float d3 = (lane < 4) ? (x3 - mean) : 0.f;
    float ss = d0 * d0 + d1 * d1 + d2 * d2 + d3 * d3;
#pragma unroll
    for (int o = 16; o; o >>= 1) ss += __shfl_xor_sync(0xffffffffu, ss, o);
    if (lane == 0) {
        float sigma = sqrtf(ss * (1.f / (NS - 1)));
        if (!(sigma < 0.1f * (*tsp))) atomicAnd(&g_flag[b], 0);
    }
    __threadfence();
    __syncthreads();
    if (threadIdx.x == 0) sh_ticket = atomicAdd(&g_done3, 1);
    __syncthreads();
    if (sh_ticket == (int)gridDim.x - 1) {
        if (threadIdx.x < BB && out_size >= BB * DD + BB)
            out[BB * DD + threadIdx.x] = g_flag[threadIdx.x] ? 1.f : 0.f;
        if (threadIdx.x == 0) g_done3 = 0;
    }
}

extern "C" void kernel_launch(void* const* d_in, const int* in_sizes, int n_in,
                              void* d_out, int out_size) {
    const float* xt      = (const float*)d_in[0];
    const float* live_x0 = (const float*)d_in[1];
    const float* live_ll = (const float*)d_in[2];
    const float* x0      = (const float*)d_in[3];
    const float* ll      = (const float*)d_in[4];
    const float* tsp     = (const float*)d_in[5];
    const int*   bidx    = (const int*)d_in[6];
    float* out = (float*)d_out;

    k_fused<<<TOTB, 256>>>(xt, live_x0, live_ll, x0, ll, tsp, bidx);

    dim3 g2(NS + 1, BB);
    k_boot<<<g2, 256>>>(xt, live_x0, x0, bidx, tsp, out);

    k_conv<<<256, 256>>>(tsp, out, out_size);
}

// round 8
// speedup vs baseline: 2.3690x; 1.2603x over previous
#include <cuda_runtime.h>
#include <math.h>

#define BB 8
#define DD 256
#define NL 10000
#define KN 32
#define KC 10032
#define NS 100

#define HISTB (NS * BB)            // 800 histogram CTAs
#define QPB   (KC / 4)             // 2508 quads per b
#define LOGB  (BB * QPB / 8)       // 2508 logits CTAs (8 quads each)
#define TOTB  (HISTB + LOGB)

// scratch (no allocations allowed)
__device__ float g_logits[BB * KC];            // for slow path only
__device__ float g_bootT[BB * DD * NS];        // [(b*DD+d)*NS + n]
__device__ int   g_cnt[NS * BB * 32];          // per-sample new-particle counts
__device__ unsigned g_MliveU[BB];              // encoded max live logit (0 = -inf; reset by k_final)

__device__ __forceinline__ unsigned fenc(float f) {
    unsigned u = __float_as_uint(f);
    return (u & 0x80000000u) ? ~u : (u | 0x80000000u);
}
__device__ __forceinline__ float fdec(unsigned u) {
    return (u & 0x80000000u) ? __uint_as_float(u & 0x7FFFFFFFu) : __uint_as_float(~u);
}

__device__ __forceinline__ float dsq(float4 a, float4 c) {
    float d0 = a.x - c.x, d1 = a.y - c.y, d2 = a.z - c.z, d3 = a.w - c.w;
    return d0 * d0 + d1 * d1 + d2 * d2 + d3 * d3;
}

__device__ __forceinline__ float blockMax256(float v, float* red) {
#pragma unroll
    for (int o = 16; o; o >>= 1) v = fmaxf(v, __shfl_xor_sync(0xffffffffu, v, o));
    int wid = threadIdx.x >> 5;
    if ((threadIdx.x & 31) == 0) red[wid] = v;
    __syncthreads();
    if (threadIdx.x < 32) {
        float x = (threadIdx.x < 8) ? red[threadIdx.x] : -INFINITY;
#pragma unroll
        for (int o = 4; o; o >>= 1) x = fmaxf(x, __shfl_xor_sync(0xffffffffu, x, o));
        if (threadIdx.x == 0) red[0] = x;
    }
    __syncthreads();
    v = red[0];
    __syncthreads();
    return v;
}

__device__ __forceinline__ float blockSum256(float v, float* red) {
#pragma unroll
    for (int o = 16; o; o >>= 1) v += __shfl_xor_sync(0xffffffffu, v, o);
    int wid = threadIdx.x >> 5;
    if ((threadIdx.x & 31) == 0) red[wid] = v;
    __syncthreads();
    if (threadIdx.x < 32) {
        float x = (threadIdx.x < 8) ? red[threadIdx.x] : 0.f;
#pragma unroll
        for (int o = 4; o; o >>= 1) x += __shfl_xor_sync(0xffffffffu, x, o);
        if (threadIdx.x == 0) red[0] = x;
    }
    __syncthreads();
    v = red[0];
    __syncthreads();
    return v;
}

// ---------- kernel 1: fused logits (+live max) + idx histogram ----------
__global__ void k_fused(const float* __restrict__ xt,
                        const float* __restrict__ live_x0,
                        const float* __restrict__ live_ll,
                        const float* __restrict__ ll,
                        const float* __restrict__ tsp,
                        const int* __restrict__ bidx) {
    __shared__ int cnt32[32];
    int bid = blockIdx.x, t = threadIdx.x;

    if (bid < HISTB) {
        // histogram of idx over the new-particle range [NL, KC)
        int n = bid >> 3, b = bid & 7;
        if (t < 32) cnt32[t] = 0;
        __syncthreads();
        const uint4* src = (const uint4*)(bidx + ((size_t)n * BB + b) * KC);
        for (int i = t; i < KC / 4; i += 256) {
            uint4 v = src[i];
            int s0 = (int)v.x - NL, s1 = (int)v.y - NL;
            int s2 = (int)v.z - NL, s3 = (int)v.w - NL;
            if (s0 >= 0) atomicAdd(&cnt32[s0], 1);
            if (s1 >= 0) atomicAdd(&cnt32[s1], 1);
            if (s2 >= 0) atomicAdd(&cnt32[s2], 1);
            if (s3 >= 0) atomicAdd(&cnt32[s3], 1);
        }
        __syncthreads();
        if (t < 32) g_cnt[((size_t)n * BB + b) * 32 + t] = cnt32[t];
        return;
    }

    // logits: 4 rows per warp
    int q = (bid - HISTB) * 8 + (t >> 5);
    int lane = t & 31;
    int b = q / QPB;
    int k0 = (q - b * QPB) * 4;
    if (k0 >= NL) {  // new particles: logits = ll exactly (cancellation)
        if (lane < 4) g_logits[(size_t)b * KC + k0 + lane] = ll[b * KN + (k0 - NL) + lane];
        return;
    }
    const float4* r0 = (const float4*)(live_x0 + ((size_t)b * NL + k0) * DD);
    const float4* r1 = r0 + (DD / 4);
    const float4* r2 = r1 + (DD / 4);
    const float4* r3 = r2 + (DD / 4);
    const float4* xtr = (const float4*)(xt + (size_t)b * DD);
    float4 c0 = xtr[lane], c1 = xtr[lane + 32];
    float4 a00 = r0[lane], a01 = r0[lane + 32];
    float4 a10 = r1[lane], a11 = r1[lane + 32];
    float4 a20 = r2[lane], a21 = r2[lane + 32];
    float4 a30 = r3[lane], a31 = r3[lane + 32];
    float s0 = dsq(a00, c0) + dsq(a01, c1);
    float s1 = dsq(a10, c0) + dsq(a11, c1);
    float s2 = dsq(a20, c0) + dsq(a21, c1);
    float s3 = dsq(a30, c0) + dsq(a31, c1);
#pragma unroll
    for (int o = 16; o; o >>= 1) {
        s0 += __shfl_xor_sync(0xffffffffu, s0, o);
        s1 += __shfl_xor_sync(0xffffffffu, s1, o);
        s2 += __shfl_xor_sync(0xffffffffu, s2, o);
        s3 += __shfl_xor_sync(0xffffffffu, s3, o);
    }
    if (lane == 0) {
        float ts = *tsp;
        float inv2 = 0.5f / (ts * ts), lg = logf(ts);
        size_t base = (size_t)b * KC + k0;
        const float* lr = live_ll + (size_t)b * NL + k0;
        float l0 = lr[0] - s0 * inv2 - lg;
        float l1 = lr[1] - s1 * inv2 - lg;
        float l2 = lr[2] - s2 * inv2 - lg;
        float l3 = lr[3] - s3 * inv2 - lg;
        g_logits[base] = l0; g_logits[base + 1] = l1;
        g_logits[base + 2] = l2; g_logits[base + 3] = l3;
        float lm = fmaxf(fmaxf(l0, l1), fmaxf(l2, l3));
        atomicMax(&g_MliveU[b], fenc(lm));
    }
}

// ---------- kernel 2: bootstrap + final score (grid = [NS+1, B]) ----------
__global__ void k_boot(const float* __restrict__ xt,
                       const float* __restrict__ live_x0,
                       const float* __restrict__ x0,
                       const float* __restrict__ ll,
                       const int* __restrict__ bidx,
                       const float* __restrict__ tsp,
                       float* __restrict__ out) {
    __shared__ float warr[32];
    __shared__ float shmz[2];
    __shared__ float red[8];
    int n = blockIdx.x, b = blockIdx.y, t = threadIdx.x;
    bool is_score = (n == NS);

    // warp 0: active weights from ll + counts (new particles only)
    if (t < 32) {
        int c = is_score ? 1 : g_cnt[((size_t)n * BB + b) * 32 + t];
        float lv = ll[b * KN + t];
        float lm = (c > 0) ? lv : -INFINITY;
        float m = lm;
#pragma unroll
        for (int o = 16; o; o >>= 1) m = fmaxf(m, __shfl_xor_sync(0xffffffffu, m, o));
        float w = (c > 0) ? (float)c * expf(lv - m) : 0.f;
        float z = w;
#pragma unroll
        for (int o = 16; o; o >>= 1) z += __shfl_xor_sync(0xffffffffu, z, o);
        warr[t] = w;
        if (t == 0) { shmz[0] = m; shmz[1] = z; }
    }
    __syncthreads();
    float m = shmz[0], z = shmz[1];
    float Mlive = fdec(g_MliveU[b]);
    float ts = *tsp;
    // all live weights underflow to exact 0 iff Mlive - m <= -90 (f32 expf cutoff ~ -104)
    bool fast = (m > -INFINITY) && (Mlive <= m - 90.f);

    float acc = 0.f;
    if (fast) {
        const float* xb = x0 + (size_t)b * KN * DD + t;
#pragma unroll
        for (int j = 0; j < KN; j += 4) {
            float v0 = xb[(j + 0) * DD];
            float v1 = xb[(j + 1) * DD];
            float v2 = xb[(j + 2) * DD];
            float v3 = xb[(j + 3) * DD];
            acc = fmaf(warr[j + 0], v0, acc);
            acc = fmaf(warr[j + 1], v1, acc);
            acc = fmaf(warr[j + 2], v2, acc);
            acc = fmaf(warr[j + 3], v3, acc);
        }
    } else {
        // exact slow path (never taken with this data)
        const int* idx = bidx + ((size_t)n * BB + b) * KC;
        const float* L = g_logits + (size_t)b * KC;
        float mm = -INFINITY;
        if (is_score) { for (int k = t; k < KC; k += 256) mm = fmaxf(mm, L[k]); }
        else          { for (int i = t; i < KC; i += 256) mm = fmaxf(mm, L[idx[i]]); }
        mm = blockMax256(mm, red);
        float zz = 0.f;
        if (is_score) { for (int k = t; k < KC; k += 256) zz += expf(L[k] - mm); }
        else          { for (int i = t; i < KC; i += 256) zz += expf(L[idx[i]] - mm); }
        z = blockSum256(zz, red);
        for (int i = 0; i < KC; i++) {
            int k = is_score ? i : idx[i];
            float w = expf(L[k] - mm);
            if (w != 0.f) {
                const float* r = (k < NL) ? live_x0 + ((size_t)b * NL + k) * DD
                                          : x0 + ((size_t)b * KN + (k - NL)) * DD;
                acc = fmaf(w, r[t], acc);
            }
        }
    }

    float val = acc / (z * ts) - xt[(size_t)b * DD + t] / ts;
    if (is_score) out[(size_t)b * DD + t] = val;
    else          g_bootT[((size_t)b * DD + t) * NS + n] = val;
}

// ---------- kernel 3: per-(b,d) std (ddof=1) + flags + replay reset ----------
__global__ void k_final(const float* __restrict__ tsp, float* __restrict__ out, int out_size) {
    int b = blockIdx.x, d = threadIdx.x;
    const float* p = g_bootT + ((size_t)b * DD + d) * NS;
    float x[NS];
    const float4* p4 = (const float4*)p;
#pragma unroll
    for (int i = 0; i < NS / 4; i++) {
        float4 v = p4[i];
        x[i * 4] = v.x; x[i * 4 + 1] = v.y; x[i * 4 + 2] = v.z; x[i * 4 + 3] = v.w;
    }
    float s = 0.f;
#pragma unroll
    for (int i = 0; i < NS; i++) s += x[i];
    float mean = s * (1.f / NS);
    float q = 0.f;
#pragma unroll
    for (int i = 0; i < NS; i++) { float dv = x[i] - mean; q = fmaf(dv, dv, q); }
    float sigma = sqrtf(q * (1.f / (NS - 1)));
    int ok = sigma < 0.1f * (*tsp);
    int all = __syncthreads_and(ok);
    if (d == 0) {
        if (out_size >= BB * DD + BB) out[BB * DD + b] = all ? 1.f : 0.f;
        g_MliveU[b] = 0u;  // reset for next graph replay
    }
}

extern "C" void kernel_launch(void* const* d_in, const int* in_sizes, int n_in,
                              void* d_out, int out_size) {
    const float* xt      = (const float*)d_in[0];
    const float* live_x0 = (const float*)d_in[1];
    const float* live_ll = (const float*)d_in[2];
    const float* x0      = (const float*)d_in[3];
    const float* ll      = (const float*)d_in[4];
    const float* tsp     = (const float*)d_in[5];
    const int*   bidx    = (const int*)d_in[6];
    float* out = (float*)d_out;

    k_fused<<<TOTB, 256>>>(xt, live_x0, live_ll, ll, tsp, bidx);

    dim3 g2(NS + 1, BB);
    k_boot<<<g2, 256>>>(xt, live_x0, x0, ll, bidx, tsp, out);

    k_final<<<BB, 256>>>(tsp, out, out_size);
}